// round 14
// baseline (speedup 1.0000x reference)
#include <cuda_runtime.h>
#include <cuda_fp16.h>
#include <math.h>
#include <stdint.h>

#define N_SP 4096
#define C_IN 256
#define CQ   32
#define BATCH 4

// d_out layout (floats): q[0], k[524288], v[1048576], attended[5242880]
#define Q_OFF 0
#define K_OFF 524288
#define V_OFF 1048576
#define A_OFF 5242880

// Scratch (device globals: allowed; no dynamic allocation)
__device__ __half g_kh[BATCH * CQ   * N_SP];   // 1 MB  fp16 k
__device__ __half g_vh[BATCH * C_IN * N_SP];   // 8 MB  fp16 v
__device__ __half g_ah[BATCH * C_IN * N_SP];   // 8 MB  fp16 attn out
__device__ float  g_proj[BATCH * C_IN * N_SP]; // 16 MB proj out (norm input)

// ---------------------------------------------------------------------------
// mma.sync / cp.async helpers (sm_80+ generic PTX -> legal at compute_103)
// ---------------------------------------------------------------------------
__device__ __forceinline__ void mma_f16(
    float& d0, float& d1, float& d2, float& d3,
    uint32_t a0, uint32_t a1, uint32_t a2, uint32_t a3,
    uint32_t b0, uint32_t b1)
{
    asm volatile(
        "mma.sync.aligned.m16n8k16.row.col.f32.f16.f16.f32 "
        "{%0,%1,%2,%3}, {%4,%5,%6,%7}, {%8,%9}, {%0,%1,%2,%3};"
        : "+f"(d0), "+f"(d1), "+f"(d2), "+f"(d3)
        : "r"(a0), "r"(a1), "r"(a2), "r"(a3), "r"(b0), "r"(b1));
}
__device__ __forceinline__ uint32_t h2u(__half2 h) {
    return *reinterpret_cast<uint32_t*>(&h);
}
__device__ __forceinline__ uint32_t s2u(const void* p) {
    return (uint32_t)__cvta_generic_to_shared(p);
}
__device__ __forceinline__ void cp_async16(uint32_t smem_dst, const void* gsrc) {
    asm volatile("cp.async.cg.shared.global [%0], [%1], 16;"
                 :: "r"(smem_dst), "l"(gsrc) : "memory");
}

// ---------------------------------------------------------------------------
// Kernel 1: QKV projection GEMM, fp16 mma. (R12 winner, unchanged)
// ---------------------------------------------------------------------------
#define QW_S 20
#define QX_S 264

__global__ __launch_bounds__(256) void qkv_kernel(
    const float* __restrict__ x,
    const float* __restrict__ Wq,
    const float* __restrict__ Wk,
    const float* __restrict__ Wv,
    float* __restrict__ out)
{
    __shared__ __half2 Wsh[64 * QW_S];
    __shared__ __half2 Xsh[16 * QX_S];

    const int b  = blockIdx.z;
    const int mt = blockIdx.y;
    const int n0 = blockIdx.x * 256;

    const int t    = threadIdx.x;
    const int w    = t >> 5;
    const int lane = t & 31;
    const int gr   = lane >> 2;
    const int t4   = lane & 3;
    const int wm   = w >> 2;
    const int wn   = w & 3;

    const float* xb = x + (size_t)b * C_IN * N_SP;

    float d[2][8][4];
#pragma unroll
    for (int mf = 0; mf < 2; mf++)
#pragma unroll
        for (int nf = 0; nf < 8; nf++)
#pragma unroll
            for (int j = 0; j < 4; j++) d[mf][nf][j] = 0.f;

    const int wrow = t >> 2;
    const int wj   = (t & 3) * 4;

    for (int c0 = 0; c0 < C_IN; c0 += 32) {
        __syncthreads();
        {
            const int r = mt * 64 + wrow;
            const float* wp;
            if (r < 32)      wp = Wq + (size_t)r * C_IN;
            else if (r < 64) wp = Wk + (size_t)(r - 32) * C_IN;
            else             wp = Wv + (size_t)(r - 64) * C_IN;
            wp += c0 + 2 * wj;
            float4 w0 = *(const float4*)wp;
            float4 w1 = *(const float4*)(wp + 4);
            __half2* dst = &Wsh[wrow * QW_S + wj];
            dst[0] = __floats2half2_rn(w0.x, w0.y);
            dst[1] = __floats2half2_rn(w0.z, w0.w);
            dst[2] = __floats2half2_rn(w1.x, w1.y);
            dst[3] = __floats2half2_rn(w1.z, w1.w);
        }
#pragma unroll
        for (int cc = 0; cc < 2; cc++) {
            const int c2 = w + 8 * cc;
            const float* r0 = &xb[(size_t)(c0 + 2 * c2) * N_SP + n0];
            const float* r1 = &xb[(size_t)(c0 + 2 * c2 + 1) * N_SP + n0];
            __half2* dst = &Xsh[c2 * QX_S];
#pragma unroll
            for (int h = 0; h < 2; h++) {
                const int n = 4 * lane + 128 * h;
                const float4 a  = *(const float4*)&r0[n];
                const float4 bb = *(const float4*)&r1[n];
                dst[n + 0] = __floats2half2_rn(a.x, bb.x);
                dst[n + 1] = __floats2half2_rn(a.y, bb.y);
                dst[n + 2] = __floats2half2_rn(a.z, bb.z);
                dst[n + 3] = __floats2half2_rn(a.w, bb.w);
            }
        }
        __syncthreads();

#pragma unroll
        for (int ks = 0; ks < 2; ks++) {
            uint32_t a[2][4];
#pragma unroll
            for (int mf = 0; mf < 2; mf++) {
                const int r0 = (32 * wm + 16 * mf + gr) * QW_S + 8 * ks + t4;
                a[mf][0] = h2u(Wsh[r0]);
                a[mf][1] = h2u(Wsh[r0 + 8 * QW_S]);
                a[mf][2] = h2u(Wsh[r0 + 4]);
                a[mf][3] = h2u(Wsh[r0 + 8 * QW_S + 4]);
            }
#pragma unroll
            for (int nf = 0; nf < 8; nf++) {
                const int nc = 64 * wn + 8 * nf + gr;
                const uint32_t b0 = h2u(Xsh[(8 * ks + t4) * QX_S + nc]);
                const uint32_t b1 = h2u(Xsh[(8 * ks + t4 + 4) * QX_S + nc]);
                mma_f16(d[0][nf][0], d[0][nf][1], d[0][nf][2], d[0][nf][3],
                        a[0][0], a[0][1], a[0][2], a[0][3], b0, b1);
                mma_f16(d[1][nf][0], d[1][nf][1], d[1][nf][2], d[1][nf][3],
                        a[1][0], a[1][1], a[1][2], a[1][3], b0, b1);
            }
        }
    }

#pragma unroll
    for (int mf = 0; mf < 2; mf++) {
#pragma unroll
        for (int rr = 0; rr < 2; rr++) {
            const int r = mt * 64 + 32 * wm + 16 * mf + gr + 8 * rr;
            float* dst;
            __half* hdst = nullptr;
            if (r < 32)      { dst = out + Q_OFF + ((size_t)b * CQ + r) * N_SP; }
            else if (r < 64) { dst = out + K_OFF + ((size_t)b * CQ + (r - 32)) * N_SP;
                               hdst = g_kh + ((size_t)b * CQ + (r - 32)) * N_SP; }
            else             { dst = out + V_OFF + ((size_t)b * C_IN + (r - 64)) * N_SP;
                               hdst = g_vh + ((size_t)b * C_IN + (r - 64)) * N_SP; }
#pragma unroll
            for (int nf = 0; nf < 8; nf++) {
                const int nc = n0 + 64 * wn + 8 * nf + 2 * t4;
                const float v0 = d[mf][nf][2 * rr];
                const float v1 = d[mf][nf][2 * rr + 1];
                *(float2*)&dst[nc] = make_float2(v0, v1);
                if (hdst) *(__half2*)&hdst[nc] = __floats2half2_rn(v0, v1);
            }
        }
    }
}

// ---------------------------------------------------------------------------
// Kernel 2: flash attention, fp16 mma, register-resident P.
// Warp w: GEMM1 computes S rows 16w..16w+15; after exp, packed half2 regs are
// DIRECTLY the GEMM2 B-frags (each warp's GEMM2 covers its own 16 q-cols x
// all 256 c-rows). No Ptp smem. V and K double-buffered; V via cp.async
// overlapped with GEMM1(i)+GEMM2(i); K(i+1) LDG hoisted before GEMM1(i).
// 2 barriers per tile.
// ---------------------------------------------------------------------------
#define SV 68
#define SK 136
#define VBUF_H2 (256 * SV)
#define KBUF_H2 (16 * SK)
#define ATTN_SMEM_BYTES ((2 * VBUF_H2 + 2 * KBUF_H2) * 4)

__global__ __launch_bounds__(256, 1) void attn_kernel(const float* __restrict__ qbuf)
{
    extern __shared__ __half2 smemh[];
    __half2* vbuf[2] = { smemh, smemh + VBUF_H2 };
    __half2* kbuf[2] = { smemh + 2 * VBUF_H2, smemh + 2 * VBUF_H2 + KBUF_H2 };
    __shared__ float l_sm[128];

    const int t    = threadIdx.x;
    const int w    = t >> 5;
    const int lane = t & 31;
    const int gr   = lane >> 2;
    const int t4   = lane & 3;

    const int b  = blockIdx.y;
    const int n0 = blockIdx.x * 128;
    const float scale = 0.1767766952966369f;  // 32^-0.5

    const float* q   = qbuf + (size_t)b * CQ * N_SP;
    const __half* kb = g_kh + (size_t)b * CQ   * N_SP;
    const __half* vb = g_vh + (size_t)b * C_IN * N_SP;

    // --- Q fragments (persistent, fp16): 2 k16-steps ---
    uint32_t qa[2][4];
    {
        const int rA = n0 + 16 * w + gr;
        const int rB = rA + 8;
#pragma unroll
        for (int ks = 0; ks < 2; ks++) {
            const int c0 = 16 * ks + 2 * t4;
            qa[ks][0] = h2u(__floats2half2_rn(q[(size_t)c0 * N_SP + rA] * scale,
                                              q[(size_t)(c0 + 1) * N_SP + rA] * scale));
            qa[ks][1] = h2u(__floats2half2_rn(q[(size_t)c0 * N_SP + rB] * scale,
                                              q[(size_t)(c0 + 1) * N_SP + rB] * scale));
            qa[ks][2] = h2u(__floats2half2_rn(q[(size_t)(c0 + 8) * N_SP + rA] * scale,
                                              q[(size_t)(c0 + 9) * N_SP + rA] * scale));
            qa[ks][3] = h2u(__floats2half2_rn(q[(size_t)(c0 + 8) * N_SP + rB] * scale,
                                              q[(size_t)(c0 + 9) * N_SP + rB] * scale));
        }
    }

    // O^T accumulators: warp covers c 0..255 (16 mf) x q 16w..16w+15 (2 qb)
    float d[16][2][4];
#pragma unroll
    for (int mf = 0; mf < 16; mf++)
#pragma unroll
        for (int qb = 0; qb < 2; qb++)
#pragma unroll
            for (int j = 0; j < 4; j++) d[mf][qb][j] = 0.f;

    float l0 = 0.f, l1 = 0.f;

    // K staging thread roles
    const int kc2 = t >> 4;            // 0..15
    const int kmb = (t & 15) * 8;      // 0..120

    // --- prologue: V(0) + K(0) ---
#pragma unroll
    for (int i = 0; i < 16; i++) {
        const int fl = t + 256 * i;
        const int c  = fl >> 4;
        const int j  = fl & 15;
        cp_async16(s2u(&vbuf[0][c * SV + 4 * j]), &vb[(size_t)c * N_SP + 8 * j]);
    }
    asm volatile("cp.async.commit_group;" ::: "memory");
    {
        uint4 ra = *(const uint4*)&kb[(size_t)(2 * kc2) * N_SP + kmb];
        uint4 rb = *(const uint4*)&kb[(size_t)(2 * kc2 + 1) * N_SP + kmb];
        const __half* ha = (const __half*)&ra;
        const __half* hb = (const __half*)&rb;
        __half2* dst = &kbuf[0][kc2 * SK + kmb];
#pragma unroll
        for (int j = 0; j < 8; j++) dst[j] = __halves2half2(ha[j], hb[j]);
    }
    asm volatile("cp.async.wait_group 0;" ::: "memory");
    __syncthreads();

    for (int it = 0; it < 32; it++) {
        const int cur = it & 1;
        const int nxt = cur ^ 1;
        const int m1 = (it + 1) * 128;

        // --- issue V(i+1) cp.async + K(i+1) LDG (latency hidden by GEMM1) ---
        uint4 kra, krb;
        if (it < 31) {
#pragma unroll
            for (int i = 0; i < 16; i++) {
                const int fl = t + 256 * i;
                const int c  = fl >> 4;
                const int j  = fl & 15;
                cp_async16(s2u(&vbuf[nxt][c * SV + 4 * j]),
                           &vb[(size_t)c * N_SP + m1 + 8 * j]);
            }
            asm volatile("cp.async.commit_group;" ::: "memory");
            kra = *(const uint4*)&kb[(size_t)(2 * kc2) * N_SP + m1 + kmb];
            krb = *(const uint4*)&kb[(size_t)(2 * kc2 + 1) * N_SP + m1 + kmb];
        }

        // --- GEMM1 + softmax: P stays in registers (hh = GEMM2 B-frags) ---
        uint32_t hh[16][2];
#pragma unroll
        for (int nf = 0; nf < 16; nf++) {
            float s0 = 0.f, s1 = 0.f, s2 = 0.f, s3 = 0.f;
            const int m = 8 * nf + gr;
#pragma unroll
            for (int ks = 0; ks < 2; ks++) {
                const uint32_t b0 = h2u(kbuf[cur][(t4 + 8 * ks) * SK + m]);
                const uint32_t b1 = h2u(kbuf[cur][(t4 + 4 + 8 * ks) * SK + m]);
                mma_f16(s0, s1, s2, s3, qa[ks][0], qa[ks][1], qa[ks][2], qa[ks][3], b0, b1);
            }
            const float p0 = __expf(s0);
            const float p1 = __expf(s1);
            const float p2 = __expf(s2);
            const float p3 = __expf(s3);
            l0 += p0 + p1;
            l1 += p2 + p3;
            hh[nf][0] = h2u(__floats2half2_rn(p0, p1));
            hh[nf][1] = h2u(__floats2half2_rn(p2, p3));
        }

        // --- store K(i+1) ---
        if (it < 31) {
            const __half* ha = (const __half*)&kra;
            const __half* hb = (const __half*)&krb;
            __half2* dst = &kbuf[nxt][kc2 * SK + kmb];
#pragma unroll
            for (int j = 0; j < 8; j++) dst[j] = __halves2half2(ha[j], hb[j]);
        }

        // --- V(i) arrived + K(i+1) staged ---
        if (it < 31) { asm volatile("cp.async.wait_group 1;" ::: "memory"); }
        else         { asm volatile("cp.async.wait_group 0;" ::: "memory"); }
        __syncthreads();

        // --- GEMM2: O^T += V * P^T, B-frags from registers ---
#pragma unroll
        for (int ks = 0; ks < 8; ks++) {
#pragma unroll
            for (int mf = 0; mf < 16; mf++) {
                const int c0 = 16 * mf + gr;
                const uint32_t a0 = h2u(vbuf[cur][c0 * SV + t4 + 8 * ks]);
                const uint32_t a1 = h2u(vbuf[cur][(c0 + 8) * SV + t4 + 8 * ks]);
                const uint32_t a2 = h2u(vbuf[cur][c0 * SV + t4 + 4 + 8 * ks]);
                const uint32_t a3 = h2u(vbuf[cur][(c0 + 8) * SV + t4 + 4 + 8 * ks]);
                mma_f16(d[mf][0][0], d[mf][0][1], d[mf][0][2], d[mf][0][3],
                        a0, a1, a2, a3, hh[2 * ks][0], hh[2 * ks + 1][0]);
                mma_f16(d[mf][1][0], d[mf][1][1], d[mf][1][2], d[mf][1][3],
                        a0, a1, a2, a3, hh[2 * ks][1], hh[2 * ks + 1][1]);
            }
        }
        __syncthreads();  // all warps done with vbuf[cur]/kbuf[cur] before reuse
    }

    // --- epilogue: l broadcast + O^T/l -> g_ah (fp16) ---
    l0 += __shfl_xor_sync(0xffffffffu, l0, 1);
    l0 += __shfl_xor_sync(0xffffffffu, l0, 2);
    l1 += __shfl_xor_sync(0xffffffffu, l1, 1);
    l1 += __shfl_xor_sync(0xffffffffu, l1, 2);
    if (t4 == 0) {
        l_sm[16 * w + gr]     = l0;
        l_sm[16 * w + gr + 8] = l1;
    }
    __syncthreads();

    __half* ob = g_ah + (size_t)b * C_IN * N_SP;
#pragma unroll
    for (int qb = 0; qb < 2; qb++) {
        const int q0 = 16 * w + 8 * qb + 2 * t4;
        const float li0 = 1.f / l_sm[q0];
        const float li1 = 1.f / l_sm[q0 + 1];
#pragma unroll
        for (int mf = 0; mf < 16; mf++) {
            const int c0 = 16 * mf + gr;
            *(__half2*)&ob[(size_t)c0 * N_SP + n0 + q0] =
                __floats2half2_rn(d[mf][qb][0] * li0, d[mf][qb][1] * li1);
            *(__half2*)&ob[(size_t)(c0 + 8) * N_SP + n0 + q0] =
                __floats2half2_rn(d[mf][qb][2] * li0, d[mf][qb][3] * li1);
        }
    }
}

// ---------------------------------------------------------------------------
// Kernel 3: output projection GEMM, fp16 mma. (R12 winner, unchanged)
// ---------------------------------------------------------------------------
#define PW_S 20
#define PX_S 264

__global__ __launch_bounds__(256) void proj_kernel(const float* __restrict__ Wp)
{
    __shared__ __half2 Wsh[64 * PW_S];
    __shared__ __half2 Xsh[16 * PX_S];

    const int b  = blockIdx.z;
    const int mt = blockIdx.y;
    const int n0 = blockIdx.x * 256;

    const int t    = threadIdx.x;
    const int w    = t >> 5;
    const int lane = t & 31;
    const int gr   = lane >> 2;
    const int t4   = lane & 3;
    const int wm   = w >> 2;
    const int wn   = w & 3;

    const __half* xb = g_ah + (size_t)b * C_IN * N_SP;

    float d[2][8][4];
#pragma unroll
    for (int mf = 0; mf < 2; mf++)
#pragma unroll
        for (int nf = 0; nf < 8; nf++)
#pragma unroll
            for (int j = 0; j < 4; j++) d[mf][nf][j] = 0.f;

    const int wrow = t >> 2;
    const int wj   = (t & 3) * 4;

    for (int c0 = 0; c0 < C_IN; c0 += 32) {
        __syncthreads();
        {
            const float* wp = Wp + (size_t)(mt * 64 + wrow) * C_IN + c0 + 2 * wj;
            float4 w0 = *(const float4*)wp;
            float4 w1 = *(const float4*)(wp + 4);
            __half2* dst = &Wsh[wrow * PW_S + wj];
            dst[0] = __floats2half2_rn(w0.x, w0.y);
            dst[1] = __floats2half2_rn(w0.z, w0.w);
            dst[2] = __floats2half2_rn(w1.x, w1.y);
            dst[3] = __floats2half2_rn(w1.z, w1.w);
        }
#pragma unroll
        for (int cc = 0; cc < 2; cc++) {
            const int c2 = w + 8 * cc;
            const __half* r0 = &xb[(size_t)(c0 + 2 * c2) * N_SP + n0];
            const __half* r1 = &xb[(size_t)(c0 + 2 * c2 + 1) * N_SP + n0];
            uint4 a = *(const uint4*)&r0[8 * lane];
            uint4 bq = *(const uint4*)&r1[8 * lane];
            const __half* ha = (const __half*)&a;
            const __half* hb = (const __half*)&bq;
            __half2* dst = &Xsh[c2 * PX_S + 8 * lane];
#pragma unroll
            for (int j = 0; j < 8; j++) dst[j] = __halves2half2(ha[j], hb[j]);
        }
        __syncthreads();

#pragma unroll
        for (int ks = 0; ks < 2; ks++) {
            uint32_t a[2][4];
#pragma unroll
            for (int mf = 0; mf < 2; mf++) {
                const int r0 = (32 * wm + 16 * mf + gr) * PW_S + 8 * ks + t4;
                a[mf][0] = h2u(Wsh[r0]);
                a[mf][1] = h2u(Wsh[r0 + 8 * PW_S]);
                a[mf][2] = h2u(Wsh[r0 + 4]);
                a[mf][3] = h2u(Wsh[r0 + 8 * PW_S + 4]);
            }
#pragma unroll
            for (int nf = 0; nf < 8; nf++) {
                const int nc = 64 * wn + 8 * nf + gr;
                const uint32_t b0 = h2u(Xsh[(8 * ks + t4) * PX_S + nc]);
                const uint32_t b1 = h2u(Xsh[(8 * ks + t4 + 4) * PX_S + nc]);
                mma_f16(d[0][nf][0], d[0][nf][1], d[0][nf][2], d[0][nf][3],
                        a[0][0], a[0][1], a[0][2], a[0][3], b0, b1);
                mma_f16(d[1][nf][0], d[1][nf][1], d[1][nf][2], d[1][nf][3],
                        a[1][0], a[1][1], a[1][2], a[1][3], b0, b1);
            }
        }
    }

#pragma unroll
    for (int mf = 0; mf < 2; mf++) {
#pragma unroll
        for (int rr = 0; rr < 2; rr++) {
            const int r = mt * 64 + 32 * wm + 16 * mf + gr + 8 * rr;
            float* dst = g_proj + ((size_t)b * C_IN + r) * N_SP;
#pragma unroll
            for (int nf = 0; nf < 8; nf++) {
                const int nc = n0 + 64 * wn + 8 * nf + 2 * t4;
                *(float2*)&dst[nc] = make_float2(d[mf][nf][2 * rr], d[mf][nf][2 * rr + 1]);
            }
        }
    }
}

// ---------------------------------------------------------------------------
// Kernel 4: InstanceNorm + residual. (unchanged — canary)
// ---------------------------------------------------------------------------
__global__ __launch_bounds__(256) void norm_kernel(
    const float* __restrict__ x,
    float* __restrict__ att_out)
{
    __shared__ float red[16];

    const size_t bc = blockIdx.x;
    const float4* p4 = (const float4*)(g_proj + bc * N_SP);
    const float4* x4 = (const float4*)(x + bc * N_SP);
    float4* o4       = (float4*)(att_out + bc * N_SP);

    const int t = threadIdx.x, lane = t & 31, warp = t >> 5;

    float4 vals[4];
    float s = 0.f, sq = 0.f;
#pragma unroll
    for (int i = 0; i < 4; i++) {
        float4 v = p4[i * 256 + t];
        vals[i] = v;
        s  += v.x + v.y + v.z + v.w;
        sq += v.x * v.x + v.y * v.y + v.z * v.z + v.w * v.w;
    }
#pragma unroll
    for (int off = 16; off; off >>= 1) {
        s  += __shfl_xor_sync(0xffffffffu, s, off);
        sq += __shfl_xor_sync(0xffffffffu, sq, off);
    }
    if (lane == 0) { red[warp] = s; red[8 + warp] = sq; }
    __syncthreads();
    if (t == 0) {
        float ts = 0.f, tq = 0.f;
        for (int i = 0; i < 8; i++) { ts += red[i]; tq += red[8 + i]; }
        red[0] = ts; red[8] = tq;
    }
    __syncthreads();

    const float mean = red[0] * (1.f / N_SP);
    float var = red[8] * (1.f / N_SP) - mean * mean;
    const float rstd = rsqrtf(var + 1e-5f);

#pragma unroll
    for (int i = 0; i < 4; i++) {
        float4 v  = vals[i];
        float4 xr = x4[i * 256 + t];
        float4 r;
        r.x = (v.x - mean) * rstd + xr.x;
        r.y = (v.y - mean) * rstd + xr.y;
        r.z = (v.z - mean) * rstd + xr.z;
        r.w = (v.w - mean) * rstd + xr.w;
        o4[i * 256 + t] = r;
    }
}

// ---------------------------------------------------------------------------
extern "C" void kernel_launch(void* const* d_in, const int* in_sizes, int n_in,
                              void* d_out, int out_size)
{
    const float* x  = (const float*)d_in[0];
    const float* Wq = (const float*)d_in[1];
    const float* Wk = (const float*)d_in[2];
    const float* Wv = (const float*)d_in[3];
    const float* Wp = (const float*)d_in[4];
    float* out = (float*)d_out;

    cudaFuncSetAttribute(attn_kernel, cudaFuncAttributeMaxDynamicSharedMemorySize,
                         ATTN_SMEM_BYTES);

    qkv_kernel<<<dim3(16, 5, BATCH), 256>>>(x, Wq, Wk, Wv, out);
    attn_kernel<<<dim3(N_SP / 128, BATCH), 256, ATTN_SMEM_BYTES>>>(out + Q_OFF);
    proj_kernel<<<dim3(16, 4, BATCH), 256>>>(Wp);
    norm_kernel<<<BATCH * C_IN, 256>>>(x, out + A_OFF);
}

// round 15
// speedup vs baseline: 1.1332x; 1.1332x over previous
#include <cuda_runtime.h>
#include <cuda_fp16.h>
#include <math.h>
#include <stdint.h>

#define N_SP 4096
#define C_IN 256
#define CQ   32
#define BATCH 4

// d_out layout (floats): q[0], k[524288], v[1048576], attended[5242880]
#define Q_OFF 0
#define K_OFF 524288
#define V_OFF 1048576
#define A_OFF 5242880

// Scratch (device globals: allowed; no dynamic allocation)
__device__ __half g_kh[BATCH * CQ   * N_SP];   // 1 MB  fp16 k
__device__ __half g_vh[BATCH * C_IN * N_SP];   // 8 MB  fp16 v
__device__ __half g_ah[BATCH * C_IN * N_SP];   // 8 MB  fp16 attn out
__device__ float  g_proj[BATCH * C_IN * N_SP]; // 16 MB proj out (norm input)

// ---------------------------------------------------------------------------
// mma.sync / cp.async helpers (sm_80+ generic PTX -> legal at compute_103)
// ---------------------------------------------------------------------------
__device__ __forceinline__ void mma_f16(
    float& d0, float& d1, float& d2, float& d3,
    uint32_t a0, uint32_t a1, uint32_t a2, uint32_t a3,
    uint32_t b0, uint32_t b1)
{
    asm volatile(
        "mma.sync.aligned.m16n8k16.row.col.f32.f16.f16.f32 "
        "{%0,%1,%2,%3}, {%4,%5,%6,%7}, {%8,%9}, {%0,%1,%2,%3};"
        : "+f"(d0), "+f"(d1), "+f"(d2), "+f"(d3)
        : "r"(a0), "r"(a1), "r"(a2), "r"(a3), "r"(b0), "r"(b1));
}
__device__ __forceinline__ uint32_t h2u(__half2 h) {
    return *reinterpret_cast<uint32_t*>(&h);
}
__device__ __forceinline__ uint32_t s2u(const void* p) {
    return (uint32_t)__cvta_generic_to_shared(p);
}
__device__ __forceinline__ void cp_async16(uint32_t smem_dst, const void* gsrc) {
    asm volatile("cp.async.cg.shared.global [%0], [%1], 16;"
                 :: "r"(smem_dst), "l"(gsrc) : "memory");
}

// ---------------------------------------------------------------------------
// Kernel 1: QKV projection GEMM, fp16 mma. (R12 winner, unchanged)
// ---------------------------------------------------------------------------
#define QW_S 20
#define QX_S 264

__global__ __launch_bounds__(256) void qkv_kernel(
    const float* __restrict__ x,
    const float* __restrict__ Wq,
    const float* __restrict__ Wk,
    const float* __restrict__ Wv,
    float* __restrict__ out)
{
    __shared__ __half2 Wsh[64 * QW_S];
    __shared__ __half2 Xsh[16 * QX_S];

    const int b  = blockIdx.z;
    const int mt = blockIdx.y;
    const int n0 = blockIdx.x * 256;

    const int t    = threadIdx.x;
    const int w    = t >> 5;
    const int lane = t & 31;
    const int gr   = lane >> 2;
    const int t4   = lane & 3;
    const int wm   = w >> 2;
    const int wn   = w & 3;

    const float* xb = x + (size_t)b * C_IN * N_SP;

    float d[2][8][4];
#pragma unroll
    for (int mf = 0; mf < 2; mf++)
#pragma unroll
        for (int nf = 0; nf < 8; nf++)
#pragma unroll
            for (int j = 0; j < 4; j++) d[mf][nf][j] = 0.f;

    const int wrow = t >> 2;
    const int wj   = (t & 3) * 4;

    for (int c0 = 0; c0 < C_IN; c0 += 32) {
        __syncthreads();
        {
            const int r = mt * 64 + wrow;
            const float* wp;
            if (r < 32)      wp = Wq + (size_t)r * C_IN;
            else if (r < 64) wp = Wk + (size_t)(r - 32) * C_IN;
            else             wp = Wv + (size_t)(r - 64) * C_IN;
            wp += c0 + 2 * wj;
            float4 w0 = *(const float4*)wp;
            float4 w1 = *(const float4*)(wp + 4);
            __half2* dst = &Wsh[wrow * QW_S + wj];
            dst[0] = __floats2half2_rn(w0.x, w0.y);
            dst[1] = __floats2half2_rn(w0.z, w0.w);
            dst[2] = __floats2half2_rn(w1.x, w1.y);
            dst[3] = __floats2half2_rn(w1.z, w1.w);
        }
#pragma unroll
        for (int cc = 0; cc < 2; cc++) {
            const int c2 = w + 8 * cc;
            const float* r0 = &xb[(size_t)(c0 + 2 * c2) * N_SP + n0];
            const float* r1 = &xb[(size_t)(c0 + 2 * c2 + 1) * N_SP + n0];
            __half2* dst = &Xsh[c2 * QX_S];
#pragma unroll
            for (int h = 0; h < 2; h++) {
                const int n = 4 * lane + 128 * h;
                const float4 a  = *(const float4*)&r0[n];
                const float4 bb = *(const float4*)&r1[n];
                dst[n + 0] = __floats2half2_rn(a.x, bb.x);
                dst[n + 1] = __floats2half2_rn(a.y, bb.y);
                dst[n + 2] = __floats2half2_rn(a.z, bb.z);
                dst[n + 3] = __floats2half2_rn(a.w, bb.w);
            }
        }
        __syncthreads();

#pragma unroll
        for (int ks = 0; ks < 2; ks++) {
            uint32_t a[2][4];
#pragma unroll
            for (int mf = 0; mf < 2; mf++) {
                const int r0 = (32 * wm + 16 * mf + gr) * QW_S + 8 * ks + t4;
                a[mf][0] = h2u(Wsh[r0]);
                a[mf][1] = h2u(Wsh[r0 + 8 * QW_S]);
                a[mf][2] = h2u(Wsh[r0 + 4]);
                a[mf][3] = h2u(Wsh[r0 + 8 * QW_S + 4]);
            }
#pragma unroll
            for (int nf = 0; nf < 8; nf++) {
                const int nc = 64 * wn + 8 * nf + gr;
                const uint32_t b0 = h2u(Xsh[(8 * ks + t4) * QX_S + nc]);
                const uint32_t b1 = h2u(Xsh[(8 * ks + t4 + 4) * QX_S + nc]);
                mma_f16(d[0][nf][0], d[0][nf][1], d[0][nf][2], d[0][nf][3],
                        a[0][0], a[0][1], a[0][2], a[0][3], b0, b1);
                mma_f16(d[1][nf][0], d[1][nf][1], d[1][nf][2], d[1][nf][3],
                        a[1][0], a[1][1], a[1][2], a[1][3], b0, b1);
            }
        }
    }

#pragma unroll
    for (int mf = 0; mf < 2; mf++) {
#pragma unroll
        for (int rr = 0; rr < 2; rr++) {
            const int r = mt * 64 + 32 * wm + 16 * mf + gr + 8 * rr;
            float* dst;
            __half* hdst = nullptr;
            if (r < 32)      { dst = out + Q_OFF + ((size_t)b * CQ + r) * N_SP; }
            else if (r < 64) { dst = out + K_OFF + ((size_t)b * CQ + (r - 32)) * N_SP;
                               hdst = g_kh + ((size_t)b * CQ + (r - 32)) * N_SP; }
            else             { dst = out + V_OFF + ((size_t)b * C_IN + (r - 64)) * N_SP;
                               hdst = g_vh + ((size_t)b * C_IN + (r - 64)) * N_SP; }
#pragma unroll
            for (int nf = 0; nf < 8; nf++) {
                const int nc = n0 + 64 * wn + 8 * nf + 2 * t4;
                const float v0 = d[mf][nf][2 * rr];
                const float v1 = d[mf][nf][2 * rr + 1];
                *(float2*)&dst[nc] = make_float2(v0, v1);
                if (hdst) *(__half2*)&hdst[nc] = __floats2half2_rn(v0, v1);
            }
        }
    }
}

// ---------------------------------------------------------------------------
// Kernel 2: flash attention, fp16 mma. R12 work partition (warp = 64c x 64q,
// P via smem Ptp) + double-buffered V (cp.async, hidden under GEMM1+GEMM2)
// + double-buffered K (LDG hoisted before GEMM1, STS after).
// ---------------------------------------------------------------------------
#define SV 68
#define SK 136
#define SP 68
#define VBUF_H2 (256 * SV)
#define KBUF_H2 (16 * SK)
#define PTP_H2  (128 * SP)
#define ATTN_SMEM_BYTES ((2 * VBUF_H2 + 2 * KBUF_H2 + PTP_H2) * 4)

__global__ __launch_bounds__(256, 1) void attn_kernel(const float* __restrict__ qbuf)
{
    extern __shared__ __half2 smemh[];
    __half2* vbuf[2] = { smemh, smemh + VBUF_H2 };
    __half2* kbuf[2] = { smemh + 2 * VBUF_H2, smemh + 2 * VBUF_H2 + KBUF_H2 };
    __half2* Ptp     = smemh + 2 * VBUF_H2 + 2 * KBUF_H2;
    __shared__ float l_sm[128];

    const int t    = threadIdx.x;
    const int w    = t >> 5;
    const int lane = t & 31;
    const int gr   = lane >> 2;
    const int t4   = lane & 3;

    const int b  = blockIdx.y;
    const int n0 = blockIdx.x * 128;
    const float scale = 0.1767766952966369f;  // 32^-0.5

    const float* q   = qbuf + (size_t)b * CQ * N_SP;
    const __half* kb = g_kh + (size_t)b * CQ   * N_SP;
    const __half* vb = g_vh + (size_t)b * C_IN * N_SP;

    // --- Q fragments (persistent, fp16): 2 k16-steps ---
    uint32_t qa[2][4];
    {
        const int rA = n0 + 16 * w + gr;
        const int rB = rA + 8;
#pragma unroll
        for (int ks = 0; ks < 2; ks++) {
            const int c0 = 16 * ks + 2 * t4;
            qa[ks][0] = h2u(__floats2half2_rn(q[(size_t)c0 * N_SP + rA] * scale,
                                              q[(size_t)(c0 + 1) * N_SP + rA] * scale));
            qa[ks][1] = h2u(__floats2half2_rn(q[(size_t)c0 * N_SP + rB] * scale,
                                              q[(size_t)(c0 + 1) * N_SP + rB] * scale));
            qa[ks][2] = h2u(__floats2half2_rn(q[(size_t)(c0 + 8) * N_SP + rA] * scale,
                                              q[(size_t)(c0 + 9) * N_SP + rA] * scale));
            qa[ks][3] = h2u(__floats2half2_rn(q[(size_t)(c0 + 8) * N_SP + rB] * scale,
                                              q[(size_t)(c0 + 9) * N_SP + rB] * scale));
        }
    }

    const int cg = w & 3;
    const int qg = w >> 2;
    float d[4][8][4];
#pragma unroll
    for (int mf = 0; mf < 4; mf++)
#pragma unroll
        for (int nf = 0; nf < 8; nf++)
#pragma unroll
            for (int j = 0; j < 4; j++) d[mf][nf][j] = 0.f;

    float l0 = 0.f, l1 = 0.f;

    const int kc2 = t >> 4;            // 0..15
    const int kmb = (t & 15) * 8;      // 0..120

    // --- prologue: V(0) cp.async + K(0) synchronous ---
#pragma unroll
    for (int i = 0; i < 16; i++) {
        const int fl = t + 256 * i;
        const int c  = fl >> 4;
        const int j  = fl & 15;
        cp_async16(s2u(&vbuf[0][c * SV + 4 * j]), &vb[(size_t)c * N_SP + 8 * j]);
    }
    asm volatile("cp.async.commit_group;" ::: "memory");
    {
        uint4 ra = *(const uint4*)&kb[(size_t)(2 * kc2) * N_SP + kmb];
        uint4 rb = *(const uint4*)&kb[(size_t)(2 * kc2 + 1) * N_SP + kmb];
        const __half* ha = (const __half*)&ra;
        const __half* hb = (const __half*)&rb;
        __half2* dst = &kbuf[0][kc2 * SK + kmb];
#pragma unroll
        for (int j = 0; j < 8; j++) dst[j] = __halves2half2(ha[j], hb[j]);
    }
    __syncthreads();

    for (int it = 0; it < 32; it++) {
        const int cur = it & 1;
        const int nxt = cur ^ 1;
        const int m1 = (it + 1) * 128;

        // --- issue V(i+1) cp.async + K(i+1) LDG (hidden under GEMM1) ---
        uint4 kra, krb;
        if (it < 31) {
#pragma unroll
            for (int i = 0; i < 16; i++) {
                const int fl = t + 256 * i;
                const int c  = fl >> 4;
                const int j  = fl & 15;
                cp_async16(s2u(&vbuf[nxt][c * SV + 4 * j]),
                           &vb[(size_t)c * N_SP + m1 + 8 * j]);
            }
            asm volatile("cp.async.commit_group;" ::: "memory");
            kra = *(const uint4*)&kb[(size_t)(2 * kc2) * N_SP + m1 + kmb];
            krb = *(const uint4*)&kb[(size_t)(2 * kc2 + 1) * N_SP + m1 + kmb];
        }

        // --- GEMM1 + softmax + Ptp store (R12 partition) ---
#pragma unroll
        for (int nf = 0; nf < 16; nf++) {
            float s0 = 0.f, s1 = 0.f, s2 = 0.f, s3 = 0.f;
            const int m = 8 * nf + gr;
#pragma unroll
            for (int ks = 0; ks < 2; ks++) {
                const uint32_t b0 = h2u(kbuf[cur][(t4 + 8 * ks) * SK + m]);
                const uint32_t b1 = h2u(kbuf[cur][(t4 + 4 + 8 * ks) * SK + m]);
                mma_f16(s0, s1, s2, s3, qa[ks][0], qa[ks][1], qa[ks][2], qa[ks][3], b0, b1);
            }
            const float p0 = __expf(s0);
            const float p1 = __expf(s1);
            const float p2 = __expf(s2);
            const float p3 = __expf(s3);
            l0 += p0 + p1;
            l1 += p2 + p3;
            const int m2 = 4 * nf + t4;
            Ptp[(16 * w + gr) * SP + m2]     = __floats2half2_rn(p0, p1);
            Ptp[(16 * w + gr + 8) * SP + m2] = __floats2half2_rn(p2, p3);
        }

        // --- store K(i+1) into alternate buffer ---
        if (it < 31) {
            const __half* ha = (const __half*)&kra;
            const __half* hb = (const __half*)&krb;
            __half2* dst = &kbuf[nxt][kc2 * SK + kmb];
#pragma unroll
            for (int j = 0; j < 8; j++) dst[j] = __halves2half2(ha[j], hb[j]);
        }

        // --- V(i) arrived (V(i+1) may still be in flight) ---
        if (it < 31) { asm volatile("cp.async.wait_group 1;" ::: "memory"); }
        else         { asm volatile("cp.async.wait_group 0;" ::: "memory"); }
        __syncthreads();

        // --- GEMM2: O^T += V * P^T (R12 partition: warp = 64c x 64q) ---
#pragma unroll
        for (int ks = 0; ks < 8; ks++) {
            uint32_t bb[8][2];
#pragma unroll
            for (int nf = 0; nf < 8; nf++) {
                const int qq = 64 * qg + 8 * nf + gr;
                bb[nf][0] = h2u(Ptp[qq * SP + t4 + 8 * ks]);
                bb[nf][1] = h2u(Ptp[qq * SP + t4 + 4 + 8 * ks]);
            }
#pragma unroll
            for (int mf = 0; mf < 4; mf++) {
                const int c0 = 64 * cg + 16 * mf + gr;
                const uint32_t a0 = h2u(vbuf[cur][c0 * SV + t4 + 8 * ks]);
                const uint32_t a1 = h2u(vbuf[cur][(c0 + 8) * SV + t4 + 8 * ks]);
                const uint32_t a2 = h2u(vbuf[cur][c0 * SV + t4 + 4 + 8 * ks]);
                const uint32_t a3 = h2u(vbuf[cur][(c0 + 8) * SV + t4 + 4 + 8 * ks]);
#pragma unroll
                for (int nf = 0; nf < 8; nf++) {
                    mma_f16(d[mf][nf][0], d[mf][nf][1], d[mf][nf][2], d[mf][nf][3],
                            a0, a1, a2, a3, bb[nf][0], bb[nf][1]);
                }
            }
        }
        __syncthreads();  // Ptp + buffers safe to reuse
    }

    // --- epilogue: l broadcast + O^T/l -> g_ah (fp16) ---
    l0 += __shfl_xor_sync(0xffffffffu, l0, 1);
    l0 += __shfl_xor_sync(0xffffffffu, l0, 2);
    l1 += __shfl_xor_sync(0xffffffffu, l1, 1);
    l1 += __shfl_xor_sync(0xffffffffu, l1, 2);
    if (t4 == 0) {
        l_sm[16 * w + gr]     = l0;
        l_sm[16 * w + gr + 8] = l1;
    }
    __syncthreads();

    __half* ob = g_ah + (size_t)b * C_IN * N_SP;
#pragma unroll
    for (int nf = 0; nf < 8; nf++) {
        const int q0 = 64 * qg + 8 * nf + 2 * t4;
        const float li0 = 1.f / l_sm[q0];
        const float li1 = 1.f / l_sm[q0 + 1];
#pragma unroll
        for (int mf = 0; mf < 4; mf++) {
            const int c0 = 64 * cg + 16 * mf + gr;
            *(__half2*)&ob[(size_t)c0 * N_SP + n0 + q0] =
                __floats2half2_rn(d[mf][nf][0] * li0, d[mf][nf][1] * li1);
            *(__half2*)&ob[(size_t)(c0 + 8) * N_SP + n0 + q0] =
                __floats2half2_rn(d[mf][nf][2] * li0, d[mf][nf][3] * li1);
        }
    }
}

// ---------------------------------------------------------------------------
// Kernel 3: output projection GEMM, fp16 mma. (R12 winner, unchanged)
// ---------------------------------------------------------------------------
#define PW_S 20
#define PX_S 264

__global__ __launch_bounds__(256) void proj_kernel(const float* __restrict__ Wp)
{
    __shared__ __half2 Wsh[64 * PW_S];
    __shared__ __half2 Xsh[16 * PX_S];

    const int b  = blockIdx.z;
    const int mt = blockIdx.y;
    const int n0 = blockIdx.x * 256;

    const int t    = threadIdx.x;
    const int w    = t >> 5;
    const int lane = t & 31;
    const int gr   = lane >> 2;
    const int t4   = lane & 3;
    const int wm   = w >> 2;
    const int wn   = w & 3;

    const __half* xb = g_ah + (size_t)b * C_IN * N_SP;

    float d[2][8][4];
#pragma unroll
    for (int mf = 0; mf < 2; mf++)
#pragma unroll
        for (int nf = 0; nf < 8; nf++)
#pragma unroll
            for (int j = 0; j < 4; j++) d[mf][nf][j] = 0.f;

    const int wrow = t >> 2;
    const int wj   = (t & 3) * 4;

    for (int c0 = 0; c0 < C_IN; c0 += 32) {
        __syncthreads();
        {
            const float* wp = Wp + (size_t)(mt * 64 + wrow) * C_IN + c0 + 2 * wj;
            float4 w0 = *(const float4*)wp;
            float4 w1 = *(const float4*)(wp + 4);
            __half2* dst = &Wsh[wrow * PW_S + wj];
            dst[0] = __floats2half2_rn(w0.x, w0.y);
            dst[1] = __floats2half2_rn(w0.z, w0.w);
            dst[2] = __floats2half2_rn(w1.x, w1.y);
            dst[3] = __floats2half2_rn(w1.z, w1.w);
        }
#pragma unroll
        for (int cc = 0; cc < 2; cc++) {
            const int c2 = w + 8 * cc;
            const __half* r0 = &xb[(size_t)(c0 + 2 * c2) * N_SP + n0];
            const __half* r1 = &xb[(size_t)(c0 + 2 * c2 + 1) * N_SP + n0];
            uint4 a = *(const uint4*)&r0[8 * lane];
            uint4 bq = *(const uint4*)&r1[8 * lane];
            const __half* ha = (const __half*)&a;
            const __half* hb = (const __half*)&bq;
            __half2* dst = &Xsh[c2 * PX_S + 8 * lane];
#pragma unroll
            for (int j = 0; j < 8; j++) dst[j] = __halves2half2(ha[j], hb[j]);
        }
        __syncthreads();

#pragma unroll
        for (int ks = 0; ks < 2; ks++) {
            uint32_t a[2][4];
#pragma unroll
            for (int mf = 0; mf < 2; mf++) {
                const int r0 = (32 * wm + 16 * mf + gr) * PW_S + 8 * ks + t4;
                a[mf][0] = h2u(Wsh[r0]);
                a[mf][1] = h2u(Wsh[r0 + 8 * PW_S]);
                a[mf][2] = h2u(Wsh[r0 + 4]);
                a[mf][3] = h2u(Wsh[r0 + 8 * PW_S + 4]);
            }
#pragma unroll
            for (int nf = 0; nf < 8; nf++) {
                const int nc = 64 * wn + 8 * nf + gr;
                const uint32_t b0 = h2u(Xsh[(8 * ks + t4) * PX_S + nc]);
                const uint32_t b1 = h2u(Xsh[(8 * ks + t4 + 4) * PX_S + nc]);
                mma_f16(d[0][nf][0], d[0][nf][1], d[0][nf][2], d[0][nf][3],
                        a[0][0], a[0][1], a[0][2], a[0][3], b0, b1);
                mma_f16(d[1][nf][0], d[1][nf][1], d[1][nf][2], d[1][nf][3],
                        a[1][0], a[1][1], a[1][2], a[1][3], b0, b1);
            }
        }
    }

#pragma unroll
    for (int mf = 0; mf < 2; mf++) {
#pragma unroll
        for (int rr = 0; rr < 2; rr++) {
            const int r = mt * 64 + 32 * wm + 16 * mf + gr + 8 * rr;
            float* dst = g_proj + ((size_t)b * C_IN + r) * N_SP;
#pragma unroll
            for (int nf = 0; nf < 8; nf++) {
                const int nc = n0 + 64 * wn + 8 * nf + 2 * t4;
                *(float2*)&dst[nc] = make_float2(d[mf][nf][2 * rr], d[mf][nf][2 * rr + 1]);
            }
        }
    }
}

// ---------------------------------------------------------------------------
// Kernel 4: InstanceNorm + residual. (unchanged — canary)
// ---------------------------------------------------------------------------
__global__ __launch_bounds__(256) void norm_kernel(
    const float* __restrict__ x,
    float* __restrict__ att_out)
{
    __shared__ float red[16];

    const size_t bc = blockIdx.x;
    const float4* p4 = (const float4*)(g_proj + bc * N_SP);
    const float4* x4 = (const float4*)(x + bc * N_SP);
    float4* o4       = (float4*)(att_out + bc * N_SP);

    const int t = threadIdx.x, lane = t & 31, warp = t >> 5;

    float4 vals[4];
    float s = 0.f, sq = 0.f;
#pragma unroll
    for (int i = 0; i < 4; i++) {
        float4 v = p4[i * 256 + t];
        vals[i] = v;
        s  += v.x + v.y + v.z + v.w;
        sq += v.x * v.x + v.y * v.y + v.z * v.z + v.w * v.w;
    }
#pragma unroll
    for (int off = 16; off; off >>= 1) {
        s  += __shfl_xor_sync(0xffffffffu, s, off);
        sq += __shfl_xor_sync(0xffffffffu, sq, off);
    }
    if (lane == 0) { red[warp] = s; red[8 + warp] = sq; }
    __syncthreads();
    if (t == 0) {
        float ts = 0.f, tq = 0.f;
        for (int i = 0; i < 8; i++) { ts += red[i]; tq += red[8 + i]; }
        red[0] = ts; red[8] = tq;
    }
    __syncthreads();

    const float mean = red[0] * (1.f / N_SP);
    float var = red[8] * (1.f / N_SP) - mean * mean;
    const float rstd = rsqrtf(var + 1e-5f);

#pragma unroll
    for (int i = 0; i < 4; i++) {
        float4 v  = vals[i];
        float4 xr = x4[i * 256 + t];
        float4 r;
        r.x = (v.x - mean) * rstd + xr.x;
        r.y = (v.y - mean) * rstd + xr.y;
        r.z = (v.z - mean) * rstd + xr.z;
        r.w = (v.w - mean) * rstd + xr.w;
        o4[i * 256 + t] = r;
    }
}

// ---------------------------------------------------------------------------
extern "C" void kernel_launch(void* const* d_in, const int* in_sizes, int n_in,
                              void* d_out, int out_size)
{
    const float* x  = (const float*)d_in[0];
    const float* Wq = (const float*)d_in[1];
    const float* Wk = (const float*)d_in[2];
    const float* Wv = (const float*)d_in[3];
    const float* Wp = (const float*)d_in[4];
    float* out = (float*)d_out;

    cudaFuncSetAttribute(attn_kernel, cudaFuncAttributeMaxDynamicSharedMemorySize,
                         ATTN_SMEM_BYTES);

    qkv_kernel<<<dim3(16, 5, BATCH), 256>>>(x, Wq, Wk, Wv, out);
    attn_kernel<<<dim3(N_SP / 128, BATCH), 256, ATTN_SMEM_BYTES>>>(out + Q_OFF);
    proj_kernel<<<dim3(16, 4, BATCH), 256>>>(Wp);
    norm_kernel<<<BATCH * C_IN, 256>>>(x, out + A_OFF);
}

// round 17
// speedup vs baseline: 1.2410x; 1.0951x over previous
#include <cuda_runtime.h>
#include <cuda_fp16.h>
#include <math.h>
#include <stdint.h>

#define N_SP 4096
#define C_IN 256
#define CQ   32
#define BATCH 4

// d_out layout (floats): q[0], k[524288], v[1048576], attended[5242880]
#define Q_OFF 0
#define K_OFF 524288
#define V_OFF 1048576
#define A_OFF 5242880

// Scratch (device globals: allowed; no dynamic allocation)
__device__ __half g_kh[BATCH * CQ   * N_SP];   // 1 MB  fp16 k
__device__ __half g_vh[BATCH * C_IN * N_SP];   // 8 MB  fp16 v
__device__ __half g_ah[BATCH * C_IN * N_SP];   // 8 MB  fp16 attn out
__device__ float  g_proj[BATCH * C_IN * N_SP]; // 16 MB proj out (norm input)

// ---------------------------------------------------------------------------
// mma.sync / cp.async helpers (sm_80+ generic PTX -> legal at compute_103)
// ---------------------------------------------------------------------------
__device__ __forceinline__ void mma_f16(
    float& d0, float& d1, float& d2, float& d3,
    uint32_t a0, uint32_t a1, uint32_t a2, uint32_t a3,
    uint32_t b0, uint32_t b1)
{
    asm volatile(
        "mma.sync.aligned.m16n8k16.row.col.f32.f16.f16.f32 "
        "{%0,%1,%2,%3}, {%4,%5,%6,%7}, {%8,%9}, {%0,%1,%2,%3};"
        : "+f"(d0), "+f"(d1), "+f"(d2), "+f"(d3)
        : "r"(a0), "r"(a1), "r"(a2), "r"(a3), "r"(b0), "r"(b1));
}
__device__ __forceinline__ uint32_t h2u(__half2 h) {
    return *reinterpret_cast<uint32_t*>(&h);
}
__device__ __forceinline__ uint32_t s2u(const void* p) {
    return (uint32_t)__cvta_generic_to_shared(p);
}
__device__ __forceinline__ void cp_async16(uint32_t smem_dst, const void* gsrc) {
    asm volatile("cp.async.cg.shared.global [%0], [%1], 16;"
                 :: "r"(smem_dst), "l"(gsrc) : "memory");
}

// ---------------------------------------------------------------------------
// Kernel 1: QKV projection GEMM, fp16 mma, K-chunk 64 (2 staging buffers,
// one sync pair per 64-K). Staging/fragment layouts identical to R12.
// ---------------------------------------------------------------------------
#define QW_S 20
#define QX_S 264

__global__ __launch_bounds__(256) void qkv_kernel(
    const float* __restrict__ x,
    const float* __restrict__ Wq,
    const float* __restrict__ Wk,
    const float* __restrict__ Wv,
    float* __restrict__ out)
{
    __shared__ __half2 Wsh[2][64 * QW_S];
    __shared__ __half2 Xsh[2][16 * QX_S];

    const int b  = blockIdx.z;
    const int mt = blockIdx.y;
    const int n0 = blockIdx.x * 256;

    const int t    = threadIdx.x;
    const int w    = t >> 5;
    const int lane = t & 31;
    const int gr   = lane >> 2;
    const int t4   = lane & 3;
    const int wm   = w >> 2;
    const int wn   = w & 3;

    const float* xb = x + (size_t)b * C_IN * N_SP;

    float d[2][8][4];
#pragma unroll
    for (int mf = 0; mf < 2; mf++)
#pragma unroll
        for (int nf = 0; nf < 8; nf++)
#pragma unroll
            for (int j = 0; j < 4; j++) d[mf][nf][j] = 0.f;

    const int wrow = t >> 2;
    const int wj   = (t & 3) * 4;

    // W row pointer (resolved once)
    const float* wrow_ptr;
    {
        const int r = mt * 64 + wrow;
        if (r < 32)      wrow_ptr = Wq + (size_t)r * C_IN;
        else if (r < 64) wrow_ptr = Wk + (size_t)(r - 32) * C_IN;
        else             wrow_ptr = Wv + (size_t)(r - 64) * C_IN;
    }

    for (int c0 = 0; c0 < C_IN; c0 += 64) {
        __syncthreads();
#pragma unroll
        for (int hbuf = 0; hbuf < 2; hbuf++) {
            const int cb = c0 + 32 * hbuf;
            // --- stage W chunk [64 r][32 c] ---
            {
                const float* wp = wrow_ptr + cb + 2 * wj;
                float4 w0 = *(const float4*)wp;
                float4 w1 = *(const float4*)(wp + 4);
                __half2* dst = &Wsh[hbuf][wrow * QW_S + wj];
                dst[0] = __floats2half2_rn(w0.x, w0.y);
                dst[1] = __floats2half2_rn(w0.z, w0.w);
                dst[2] = __floats2half2_rn(w1.x, w1.y);
                dst[3] = __floats2half2_rn(w1.z, w1.w);
            }
            // --- stage X chunk [32 c][256 n], warp-per-row coalesced ---
#pragma unroll
            for (int cc = 0; cc < 2; cc++) {
                const int c2 = w + 8 * cc;
                const float* r0 = &xb[(size_t)(cb + 2 * c2) * N_SP + n0];
                const float* r1 = &xb[(size_t)(cb + 2 * c2 + 1) * N_SP + n0];
                __half2* dst = &Xsh[hbuf][c2 * QX_S];
#pragma unroll
                for (int h = 0; h < 2; h++) {
                    const int n = 4 * lane + 128 * h;
                    const float4 a  = *(const float4*)&r0[n];
                    const float4 bb = *(const float4*)&r1[n];
                    dst[n + 0] = __floats2half2_rn(a.x, bb.x);
                    dst[n + 1] = __floats2half2_rn(a.y, bb.y);
                    dst[n + 2] = __floats2half2_rn(a.z, bb.z);
                    dst[n + 3] = __floats2half2_rn(a.w, bb.w);
                }
            }
        }
        __syncthreads();

#pragma unroll
        for (int hbuf = 0; hbuf < 2; hbuf++) {
#pragma unroll
            for (int ks = 0; ks < 2; ks++) {
                uint32_t a[2][4];
#pragma unroll
                for (int mf = 0; mf < 2; mf++) {
                    const int r0 = (32 * wm + 16 * mf + gr) * QW_S + 8 * ks + t4;
                    a[mf][0] = h2u(Wsh[hbuf][r0]);
                    a[mf][1] = h2u(Wsh[hbuf][r0 + 8 * QW_S]);
                    a[mf][2] = h2u(Wsh[hbuf][r0 + 4]);
                    a[mf][3] = h2u(Wsh[hbuf][r0 + 8 * QW_S + 4]);
                }
#pragma unroll
                for (int nf = 0; nf < 8; nf++) {
                    const int nc = 64 * wn + 8 * nf + gr;
                    const uint32_t b0 = h2u(Xsh[hbuf][(8 * ks + t4) * QX_S + nc]);
                    const uint32_t b1 = h2u(Xsh[hbuf][(8 * ks + t4 + 4) * QX_S + nc]);
                    mma_f16(d[0][nf][0], d[0][nf][1], d[0][nf][2], d[0][nf][3],
                            a[0][0], a[0][1], a[0][2], a[0][3], b0, b1);
                    mma_f16(d[1][nf][0], d[1][nf][1], d[1][nf][2], d[1][nf][3],
                            a[1][0], a[1][1], a[1][2], a[1][3], b0, b1);
                }
            }
        }
    }

    // epilogue: fp32 to d_out regions; fp16 side-copies of k and v
#pragma unroll
    for (int mf = 0; mf < 2; mf++) {
#pragma unroll
        for (int rr = 0; rr < 2; rr++) {
            const int r = mt * 64 + 32 * wm + 16 * mf + gr + 8 * rr;
            float* dst;
            __half* hdst = nullptr;
            if (r < 32)      { dst = out + Q_OFF + ((size_t)b * CQ + r) * N_SP; }
            else if (r < 64) { dst = out + K_OFF + ((size_t)b * CQ + (r - 32)) * N_SP;
                               hdst = g_kh + ((size_t)b * CQ + (r - 32)) * N_SP; }
            else             { dst = out + V_OFF + ((size_t)b * C_IN + (r - 64)) * N_SP;
                               hdst = g_vh + ((size_t)b * C_IN + (r - 64)) * N_SP; }
#pragma unroll
            for (int nf = 0; nf < 8; nf++) {
                const int nc = n0 + 64 * wn + 8 * nf + 2 * t4;
                const float v0 = d[mf][nf][2 * rr];
                const float v1 = d[mf][nf][2 * rr + 1];
                *(float2*)&dst[nc] = make_float2(v0, v1);
                if (hdst) *(__half2*)&hdst[nc] = __floats2half2_rn(v0, v1);
            }
        }
    }
}

// ---------------------------------------------------------------------------
// Kernel 2: flash attention, fp16 mma; cp.async V overlap. (R12 winner,
// reverted byte-for-byte; R13/R14 pipeline variants falsified.)
// ---------------------------------------------------------------------------
#define SV 68
#define SK 136
#define SP 68
#define VSP_ELEMS (256 * SV)
#define KSP_ELEMS (16 * SK)
#define PTP_ELEMS (128 * SP)
#define ATTN_SMEM_BYTES ((VSP_ELEMS + KSP_ELEMS + PTP_ELEMS) * 4)

__global__ __launch_bounds__(256, 1) void attn_kernel(const float* __restrict__ qbuf)
{
    extern __shared__ __half2 smemh[];
    __half2* Vsp = smemh;
    __half2* Ksp = smemh + VSP_ELEMS;
    __half2* Ptp = smemh + VSP_ELEMS + KSP_ELEMS;
    __shared__ float l_sm[128];

    const int t    = threadIdx.x;
    const int w    = t >> 5;
    const int lane = t & 31;
    const int gr   = lane >> 2;
    const int t4   = lane & 3;

    const int b  = blockIdx.y;
    const int n0 = blockIdx.x * 128;
    const float scale = 0.1767766952966369f;  // 32^-0.5

    const float* q   = qbuf + (size_t)b * CQ * N_SP;
    const __half* kb = g_kh + (size_t)b * CQ   * N_SP;
    const __half* vb = g_vh + (size_t)b * C_IN * N_SP;

    uint32_t qa[2][4];
    {
        const int rA = n0 + 16 * w + gr;
        const int rB = rA + 8;
#pragma unroll
        for (int ks = 0; ks < 2; ks++) {
            const int c0 = 16 * ks + 2 * t4;
            qa[ks][0] = h2u(__floats2half2_rn(q[(size_t)c0 * N_SP + rA] * scale,
                                              q[(size_t)(c0 + 1) * N_SP + rA] * scale));
            qa[ks][1] = h2u(__floats2half2_rn(q[(size_t)c0 * N_SP + rB] * scale,
                                              q[(size_t)(c0 + 1) * N_SP + rB] * scale));
            qa[ks][2] = h2u(__floats2half2_rn(q[(size_t)(c0 + 8) * N_SP + rA] * scale,
                                              q[(size_t)(c0 + 9) * N_SP + rA] * scale));
            qa[ks][3] = h2u(__floats2half2_rn(q[(size_t)(c0 + 8) * N_SP + rB] * scale,
                                              q[(size_t)(c0 + 9) * N_SP + rB] * scale));
        }
    }

    const int cg = w & 3;
    const int qg = w >> 2;
    float d[4][8][4];
#pragma unroll
    for (int mf = 0; mf < 4; mf++)
#pragma unroll
        for (int nf = 0; nf < 8; nf++)
#pragma unroll
            for (int j = 0; j < 4; j++) d[mf][nf][j] = 0.f;

    float l0 = 0.f, l1 = 0.f;

    for (int it = 0; it < 32; it++) {
        const int m0 = it * 128;
        __syncthreads();

#pragma unroll
        for (int i = 0; i < 16; i++) {
            const int fl = t + 256 * i;
            const int c  = fl >> 4;
            const int j  = fl & 15;
            cp_async16(s2u(&Vsp[c * SV + 4 * j]), &vb[(size_t)c * N_SP + m0 + 8 * j]);
        }
        asm volatile("cp.async.commit_group;" ::: "memory");

        {
            const int c2 = t >> 4;
            const int mb = (t & 15) * 8;
            uint4 ra = *(const uint4*)&kb[(size_t)(2 * c2) * N_SP + m0 + mb];
            uint4 rb = *(const uint4*)&kb[(size_t)(2 * c2 + 1) * N_SP + m0 + mb];
            const __half* ha = (const __half*)&ra;
            const __half* hb = (const __half*)&rb;
            __half2* dst = &Ksp[c2 * SK + mb];
#pragma unroll
            for (int j = 0; j < 8; j++) dst[j] = __halves2half2(ha[j], hb[j]);
        }
        __syncthreads();

#pragma unroll
        for (int nf = 0; nf < 16; nf++) {
            float s0 = 0.f, s1 = 0.f, s2 = 0.f, s3 = 0.f;
            const int m = 8 * nf + gr;
#pragma unroll
            for (int ks = 0; ks < 2; ks++) {
                const uint32_t b0 = h2u(Ksp[(t4 + 8 * ks) * SK + m]);
                const uint32_t b1 = h2u(Ksp[(t4 + 4 + 8 * ks) * SK + m]);
                mma_f16(s0, s1, s2, s3, qa[ks][0], qa[ks][1], qa[ks][2], qa[ks][3], b0, b1);
            }
            const float p0 = __expf(s0);
            const float p1 = __expf(s1);
            const float p2 = __expf(s2);
            const float p3 = __expf(s3);
            l0 += p0 + p1;
            l1 += p2 + p3;
            const int m2 = 4 * nf + t4;
            Ptp[(16 * w + gr) * SP + m2]     = __floats2half2_rn(p0, p1);
            Ptp[(16 * w + gr + 8) * SP + m2] = __floats2half2_rn(p2, p3);
        }
        asm volatile("cp.async.wait_group 0;" ::: "memory");
        __syncthreads();

#pragma unroll
        for (int ks = 0; ks < 8; ks++) {
            uint32_t bb[8][2];
#pragma unroll
            for (int nf = 0; nf < 8; nf++) {
                const int qq = 64 * qg + 8 * nf + gr;
                bb[nf][0] = h2u(Ptp[qq * SP + t4 + 8 * ks]);
                bb[nf][1] = h2u(Ptp[qq * SP + t4 + 4 + 8 * ks]);
            }
#pragma unroll
            for (int mf = 0; mf < 4; mf++) {
                const int c0 = 64 * cg + 16 * mf + gr;
                const uint32_t a0 = h2u(Vsp[c0 * SV + t4 + 8 * ks]);
                const uint32_t a1 = h2u(Vsp[(c0 + 8) * SV + t4 + 8 * ks]);
                const uint32_t a2 = h2u(Vsp[c0 * SV + t4 + 4 + 8 * ks]);
                const uint32_t a3 = h2u(Vsp[(c0 + 8) * SV + t4 + 4 + 8 * ks]);
#pragma unroll
                for (int nf = 0; nf < 8; nf++) {
                    mma_f16(d[mf][nf][0], d[mf][nf][1], d[mf][nf][2], d[mf][nf][3],
                            a0, a1, a2, a3, bb[nf][0], bb[nf][1]);
                }
            }
        }
    }

    l0 += __shfl_xor_sync(0xffffffffu, l0, 1);
    l0 += __shfl_xor_sync(0xffffffffu, l0, 2);
    l1 += __shfl_xor_sync(0xffffffffu, l1, 1);
    l1 += __shfl_xor_sync(0xffffffffu, l1, 2);
    if (t4 == 0) {
        l_sm[16 * w + gr]     = l0;
        l_sm[16 * w + gr + 8] = l1;
    }
    __syncthreads();

    __half* ob = g_ah + (size_t)b * C_IN * N_SP;
#pragma unroll
    for (int nf = 0; nf < 8; nf++) {
        const int q0 = 64 * qg + 8 * nf + 2 * t4;
        const float li0 = 1.f / l_sm[q0];
        const float li1 = 1.f / l_sm[q0 + 1];
#pragma unroll
        for (int mf = 0; mf < 4; mf++) {
            const int c0 = 64 * cg + 16 * mf + gr;
            *(__half2*)&ob[(size_t)c0 * N_SP + n0 + q0] =
                __floats2half2_rn(d[mf][nf][0] * li0, d[mf][nf][1] * li1);
            *(__half2*)&ob[(size_t)(c0 + 8) * N_SP + n0 + q0] =
                __floats2half2_rn(d[mf][nf][2] * li0, d[mf][nf][3] * li1);
        }
    }
}

// ---------------------------------------------------------------------------
// Kernel 3: output projection GEMM, fp16 mma, K-chunk 64 (2 buffers, one
// sync pair per 64-K). Layouts identical to R12.
// ---------------------------------------------------------------------------
#define PW_S 20
#define PX_S 264

__global__ __launch_bounds__(256) void proj_kernel(const float* __restrict__ Wp)
{
    __shared__ __half2 Wsh[2][64 * PW_S];
    __shared__ __half2 Xsh[2][16 * PX_S];

    const int b  = blockIdx.z;
    const int mt = blockIdx.y;
    const int n0 = blockIdx.x * 256;

    const int t    = threadIdx.x;
    const int w    = t >> 5;
    const int lane = t & 31;
    const int gr   = lane >> 2;
    const int t4   = lane & 3;
    const int wm   = w >> 2;
    const int wn   = w & 3;

    const __half* xb = g_ah + (size_t)b * C_IN * N_SP;

    float d[2][8][4];
#pragma unroll
    for (int mf = 0; mf < 2; mf++)
#pragma unroll
        for (int nf = 0; nf < 8; nf++)
#pragma unroll
            for (int j = 0; j < 4; j++) d[mf][nf][j] = 0.f;

    const int wrow = t >> 2;
    const int wj   = (t & 3) * 4;
    const float* wrow_ptr = Wp + (size_t)(mt * 64 + wrow) * C_IN;

    for (int c0 = 0; c0 < C_IN; c0 += 64) {
        __syncthreads();
#pragma unroll
        for (int hbuf = 0; hbuf < 2; hbuf++) {
            const int cb = c0 + 32 * hbuf;
            {
                const float* wp = wrow_ptr + cb + 2 * wj;
                float4 w0 = *(const float4*)wp;
                float4 w1 = *(const float4*)(wp + 4);
                __half2* dst = &Wsh[hbuf][wrow * PW_S + wj];
                dst[0] = __floats2half2_rn(w0.x, w0.y);
                dst[1] = __floats2half2_rn(w0.z, w0.w);
                dst[2] = __floats2half2_rn(w1.x, w1.y);
                dst[3] = __floats2half2_rn(w1.z, w1.w);
            }
#pragma unroll
            for (int cc = 0; cc < 2; cc++) {
                const int c2 = w + 8 * cc;
                const __half* r0 = &xb[(size_t)(cb + 2 * c2) * N_SP + n0];
                const __half* r1 = &xb[(size_t)(cb + 2 * c2 + 1) * N_SP + n0];
                uint4 a = *(const uint4*)&r0[8 * lane];
                uint4 bq = *(const uint4*)&r1[8 * lane];
                const __half* ha = (const __half*)&a;
                const __half* hb = (const __half*)&bq;
                __half2* dst = &Xsh[hbuf][c2 * PX_S + 8 * lane];
#pragma unroll
                for (int j = 0; j < 8; j++) dst[j] = __halves2half2(ha[j], hb[j]);
            }
        }
        __syncthreads();

#pragma unroll
        for (int hbuf = 0; hbuf < 2; hbuf++) {
#pragma unroll
            for (int ks = 0; ks < 2; ks++) {
                uint32_t a[2][4];
#pragma unroll
                for (int mf = 0; mf < 2; mf++) {
                    const int r0 = (32 * wm + 16 * mf + gr) * PW_S + 8 * ks + t4;
                    a[mf][0] = h2u(Wsh[hbuf][r0]);
                    a[mf][1] = h2u(Wsh[hbuf][r0 + 8 * PW_S]);
                    a[mf][2] = h2u(Wsh[hbuf][r0 + 4]);
                    a[mf][3] = h2u(Wsh[hbuf][r0 + 8 * PW_S + 4]);
                }
#pragma unroll
                for (int nf = 0; nf < 8; nf++) {
                    const int nc = 64 * wn + 8 * nf + gr;
                    const uint32_t b0 = h2u(Xsh[hbuf][(8 * ks + t4) * PX_S + nc]);
                    const uint32_t b1 = h2u(Xsh[hbuf][(8 * ks + t4 + 4) * PX_S + nc]);
                    mma_f16(d[0][nf][0], d[0][nf][1], d[0][nf][2], d[0][nf][3],
                            a[0][0], a[0][1], a[0][2], a[0][3], b0, b1);
                    mma_f16(d[1][nf][0], d[1][nf][1], d[1][nf][2], d[1][nf][3],
                            a[1][0], a[1][1], a[1][2], a[1][3], b0, b1);
                }
            }
        }
    }

#pragma unroll
    for (int mf = 0; mf < 2; mf++) {
#pragma unroll
        for (int rr = 0; rr < 2; rr++) {
            const int r = mt * 64 + 32 * wm + 16 * mf + gr + 8 * rr;
            float* dst = g_proj + ((size_t)b * C_IN + r) * N_SP;
#pragma unroll
            for (int nf = 0; nf < 8; nf++) {
                const int nc = n0 + 64 * wn + 8 * nf + 2 * t4;
                *(float2*)&dst[nc] = make_float2(d[mf][nf][2 * rr], d[mf][nf][2 * rr + 1]);
            }
        }
    }
}

// ---------------------------------------------------------------------------
// Kernel 4: InstanceNorm + residual. (unchanged — canary)
// ---------------------------------------------------------------------------
__global__ __launch_bounds__(256) void norm_kernel(
    const float* __restrict__ x,
    float* __restrict__ att_out)
{
    __shared__ float red[16];

    const size_t bc = blockIdx.x;
    const float4* p4 = (const float4*)(g_proj + bc * N_SP);
    const float4* x4 = (const float4*)(x + bc * N_SP);
    float4* o4       = (float4*)(att_out + bc * N_SP);

    const int t = threadIdx.x, lane = t & 31, warp = t >> 5;

    float4 vals[4];
    float s = 0.f, sq = 0.f;
#pragma unroll
    for (int i = 0; i < 4; i++) {
        float4 v = p4[i * 256 + t];
        vals[i] = v;
        s  += v.x + v.y + v.z + v.w;
        sq += v.x * v.x + v.y * v.y + v.z * v.z + v.w * v.w;
    }
#pragma unroll
    for (int off = 16; off; off >>= 1) {
        s  += __shfl_xor_sync(0xffffffffu, s, off);
        sq += __shfl_xor_sync(0xffffffffu, sq, off);
    }
    if (lane == 0) { red[warp] = s; red[8 + warp] = sq; }
    __syncthreads();
    if (t == 0) {
        float ts = 0.f, tq = 0.f;
        for (int i = 0; i < 8; i++) { ts += red[i]; tq += red[8 + i]; }
        red[0] = ts; red[8] = tq;
    }
    __syncthreads();

    const float mean = red[0] * (1.f / N_SP);
    float var = red[8] * (1.f / N_SP) - mean * mean;
    const float rstd = rsqrtf(var + 1e-5f);

#pragma unroll
    for (int i = 0; i < 4; i++) {
        float4 v  = vals[i];
        float4 xr = x4[i * 256 + t];
        float4 r;
        r.x = (v.x - mean) * rstd + xr.x;
        r.y = (v.y - mean) * rstd + xr.y;
        r.z = (v.z - mean) * rstd + xr.z;
        r.w = (v.w - mean) * rstd + xr.w;
        o4[i * 256 + t] = r;
    }
}

// ---------------------------------------------------------------------------
extern "C" void kernel_launch(void* const* d_in, const int* in_sizes, int n_in,
                              void* d_out, int out_size)
{
    const float* x  = (const float*)d_in[0];
    const float* Wq = (const float*)d_in[1];
    const float* Wk = (const float*)d_in[2];
    const float* Wv = (const float*)d_in[3];
    const float* Wp = (const float*)d_in[4];
    float* out = (float*)d_out;

    cudaFuncSetAttribute(attn_kernel, cudaFuncAttributeMaxDynamicSharedMemorySize,
                         ATTN_SMEM_BYTES);

    qkv_kernel<<<dim3(16, 5, BATCH), 256>>>(x, Wq, Wk, Wv, out);
    attn_kernel<<<dim3(N_SP / 128, BATCH), 256, ATTN_SMEM_BYTES>>>(out + Q_OFF);
    proj_kernel<<<dim3(16, 4, BATCH), 256>>>(Wp);
    norm_kernel<<<BATCH * C_IN, 256>>>(x, out + A_OFF);
}